// round 1
// baseline (speedup 1.0000x reference)
#include <cuda_runtime.h>
#include <math.h>

// Problem dims (fixed by the reference)
#define B_  1024
#define D_  512
#define H_  2048
#define NSTEPS 16

// -------- device scratch (allocation-free: static __device__ globals) --------
__device__ float g_y   [B_ * D_];   // current state y
__device__ float g_ytmp[B_ * D_];   // y + c*k  (input to next f eval)
__device__ float g_acc [B_ * D_];   // RK4 accumulator k1 + 2k2 + 2k3
__device__ float g_h   [B_ * H_];   // hidden activations tanh(...)

// ---------------------------------------------------------------------------
__global__ void init_y_kernel(const float* __restrict__ x) {
    int i = blockIdx.x * blockDim.x + threadIdx.x;
    if (i < B_ * D_) g_y[i] = x[i];
}

// ---------------------------------------------------------------------------
// Kernel A:  g_h[M,N] = tanh( Ain[M,K] @ W1[K,N] + b1[N] + t )
//   M=1024 (B), K=512 (D), N=2048 (H)
//   Tile: BM=64, BN=128, BK=8, 256 threads, 4x8 per thread. Grid (16,16)=256 blocks.
//   in_sel: 0 -> read g_y, 1 -> read g_ytmp
__global__ __launch_bounds__(256) void gemm_tanh_kernel(
    const float* __restrict__ W1, const float* __restrict__ b1,
    float t, int in_sel)
{
    const int M = B_, K = D_, N = H_;
    const int BM = 64, BN = 128, BK = 8;

    __shared__ float As[BK][BM + 2];   // +2 pad kills store-phase bank conflicts
    __shared__ float Bs[BK][BN];

    const float* __restrict__ Ain = in_sel ? g_ytmp : g_y;

    int tid = threadIdx.x;
    int bn0 = blockIdx.x * BN;
    int bm0 = blockIdx.y * BM;
    int tc  = tid & 15;        // 0..15 -> 8 output cols each
    int tr  = tid >> 4;        // 0..15 -> 4 output rows each

    float acc[4][8];
#pragma unroll
    for (int i = 0; i < 4; i++)
#pragma unroll
        for (int j = 0; j < 8; j++) acc[i][j] = 0.f;

    for (int k0 = 0; k0 < K; k0 += BK) {
        // A tile 64x8 = 128 float4 (threads 0..127)
        if (tid < 128) {
            int r = tid >> 1;
            int c = (tid & 1) * 4;
            float4 v = *reinterpret_cast<const float4*>(&Ain[(bm0 + r) * K + k0 + c]);
            As[c + 0][r] = v.x; As[c + 1][r] = v.y;
            As[c + 2][r] = v.z; As[c + 3][r] = v.w;
        }
        // B tile 8x128 = 256 float4
        {
            int r = tid >> 5;            // 0..7
            int c = (tid & 31) * 4;      // 0..124
            float4 v = *reinterpret_cast<const float4*>(&W1[(k0 + r) * N + bn0 + c]);
            *reinterpret_cast<float4*>(&Bs[r][c]) = v;
        }
        __syncthreads();

#pragma unroll
        for (int k = 0; k < BK; k++) {
            float a[4], b[8];
#pragma unroll
            for (int i = 0; i < 4; i++) a[i] = As[k][tr * 4 + i];
#pragma unroll
            for (int j = 0; j < 8; j++) b[j] = Bs[k][tc * 8 + j];
#pragma unroll
            for (int i = 0; i < 4; i++)
#pragma unroll
                for (int j = 0; j < 8; j++) acc[i][j] += a[i] * b[j];
        }
        __syncthreads();
    }

    // epilogue: tanh(acc + b1[n] + t)
#pragma unroll
    for (int i = 0; i < 4; i++) {
        int m = bm0 + tr * 4 + i;
#pragma unroll
        for (int j = 0; j < 8; j++) {
            int n = bn0 + tc * 8 + j;
            g_h[m * N + n] = tanhf(acc[i][j] + b1[n] + t);
        }
    }
}

// ---------------------------------------------------------------------------
// Kernel B:  k[M,N] = g_h[M,K] @ W2[K,N] + b2[N], fused RK4 stage epilogue
//   M=1024 (B), K=2048 (H), N=512 (D)
//   Tile: BM=64, BN=64, BK=16, 256 threads, 4x4 per thread. Grid (8,16)=128 blocks.
// mode: 0 -> k1:  acc  = k;        ytmp = y + 0.5*dt*k
//       1 -> k2:  acc += 2k;       ytmp = y + 0.5*dt*k
//       2 -> k3:  acc += 2k;       ytmp = y + dt*k
//       3 -> k4:  g_y  = y + dt/6*(acc + k)
//       4 -> k4 (final step): yout = y + dt/6*(acc + k)
__global__ __launch_bounds__(256) void gemm_rk4_kernel(
    const float* __restrict__ W2, const float* __restrict__ b2,
    float dt, int mode, float* __restrict__ yout)
{
    const int M = B_, K = H_, N = D_;
    const int BM = 64, BN = 64, BK = 16;

    __shared__ float As[BK][BM + 2];
    __shared__ float Bs[BK][BN];

    int tid = threadIdx.x;
    int bn0 = blockIdx.x * BN;
    int bm0 = blockIdx.y * BM;
    int tc  = tid & 15;        // 0..15 -> 4 output cols each
    int tr  = tid >> 4;        // 0..15 -> 4 output rows each

    float acc[4][4];
#pragma unroll
    for (int i = 0; i < 4; i++)
#pragma unroll
        for (int j = 0; j < 4; j++) acc[i][j] = 0.f;

    for (int k0 = 0; k0 < K; k0 += BK) {
        // A tile 64x16 = 256 float4
        {
            int r = tid >> 2;            // 0..63
            int c = (tid & 3) * 4;       // 0..12
            float4 v = *reinterpret_cast<const float4*>(&g_h[(bm0 + r) * K + k0 + c]);
            As[c + 0][r] = v.x; As[c + 1][r] = v.y;
            As[c + 2][r] = v.z; As[c + 3][r] = v.w;
        }
        // B tile 16x64 = 256 float4
        {
            int r = tid >> 4;            // 0..15
            int c = (tid & 15) * 4;      // 0..60
            float4 v = *reinterpret_cast<const float4*>(&W2[(k0 + r) * N + bn0 + c]);
            *reinterpret_cast<float4*>(&Bs[r][c]) = v;
        }
        __syncthreads();

#pragma unroll
        for (int k = 0; k < BK; k++) {
            float a[4], b[4];
#pragma unroll
            for (int i = 0; i < 4; i++) a[i] = As[k][tr * 4 + i];
#pragma unroll
            for (int j = 0; j < 4; j++) b[j] = Bs[k][tc * 4 + j];
#pragma unroll
            for (int i = 0; i < 4; i++)
#pragma unroll
                for (int j = 0; j < 4; j++) acc[i][j] += a[i] * b[j];
        }
        __syncthreads();
    }

    const float half_dt = 0.5f * dt;
    const float sixth_dt = dt * (1.0f / 6.0f);

#pragma unroll
    for (int i = 0; i < 4; i++) {
        int m = bm0 + tr * 4 + i;
#pragma unroll
        for (int j = 0; j < 4; j++) {
            int n = bn0 + tc * 4 + j;
            int idx = m * N + n;
            float kv = acc[i][j] + b2[n];
            if (mode == 0) {
                g_acc[idx]  = kv;
                g_ytmp[idx] = g_y[idx] + half_dt * kv;
            } else if (mode == 1) {
                g_acc[idx] += 2.0f * kv;
                g_ytmp[idx] = g_y[idx] + half_dt * kv;
            } else if (mode == 2) {
                g_acc[idx] += 2.0f * kv;
                g_ytmp[idx] = g_y[idx] + dt * kv;
            } else if (mode == 3) {
                g_y[idx]    = g_y[idx] + sixth_dt * (g_acc[idx] + kv);
            } else {
                yout[idx]   = g_y[idx] + sixth_dt * (g_acc[idx] + kv);
            }
        }
    }
}

// ---------------------------------------------------------------------------
extern "C" void kernel_launch(void* const* d_in, const int* in_sizes, int n_in,
                              void* d_out, int out_size)
{
    const float* x  = (const float*)d_in[0];   // [1024, 512]
    const float* W1 = (const float*)d_in[1];   // [512, 2048]
    const float* b1 = (const float*)d_in[2];   // [2048]
    const float* W2 = (const float*)d_in[3];   // [2048, 512]
    const float* b2 = (const float*)d_in[4];   // [512]
    float* out = (float*)d_out;                // [1024, 512]

    const float dt = 1.0f / (float)NSTEPS;

    // y <- x (re-done every replay: deterministic)
    init_y_kernel<<<(B_ * D_ + 255) / 256, 256>>>(x);

    dim3 gridA(H_ / 128, B_ / 64);   // (16,16) = 256 blocks
    dim3 gridB(D_ / 64,  B_ / 64);   // (8,16)  = 128 blocks

    for (int s = 0; s < NSTEPS; s++) {
        float t = dt * (float)s;

        // stage 1: k1 = f(t, y)
        gemm_tanh_kernel<<<gridA, 256>>>(W1, b1, t, /*in_sel=*/0);
        gemm_rk4_kernel <<<gridB, 256>>>(W2, b2, dt, /*mode=*/0, out);

        // stage 2: k2 = f(t + dt/2, y + dt/2 k1)
        gemm_tanh_kernel<<<gridA, 256>>>(W1, b1, t + 0.5f * dt, /*in_sel=*/1);
        gemm_rk4_kernel <<<gridB, 256>>>(W2, b2, dt, /*mode=*/1, out);

        // stage 3: k3 = f(t + dt/2, y + dt/2 k2)
        gemm_tanh_kernel<<<gridA, 256>>>(W1, b1, t + 0.5f * dt, /*in_sel=*/1);
        gemm_rk4_kernel <<<gridB, 256>>>(W2, b2, dt, /*mode=*/2, out);

        // stage 4: k4 = f(t + dt, y + dt k3); y' = y + dt/6 (k1+2k2+2k3+k4)
        gemm_tanh_kernel<<<gridA, 256>>>(W1, b1, t + dt, /*in_sel=*/1);
        int mode = (s == NSTEPS - 1) ? 4 : 3;
        gemm_rk4_kernel <<<gridB, 256>>>(W2, b2, dt, mode, out);
    }
}

// round 2
// speedup vs baseline: 2.1179x; 2.1179x over previous
#include <cuda_runtime.h>
#include <math.h>

// Problem dims (fixed by the reference)
#define B_  1024
#define D_  512
#define H_  2048
#define NSTEPS 16

// -------- device scratch (allocation-free: static __device__ globals) --------
__device__ float g_y   [B_ * D_];   // current state y
__device__ float g_ytmp[B_ * D_];   // y + c*k  (input to next f eval)
__device__ float g_acc [B_ * D_];   // RK4 accumulator k1 + 2k2 + 2k3
__device__ float g_h   [B_ * H_];   // hidden activations tanh(...)

// ---------------------------------------------------------------------------
__device__ __forceinline__ unsigned f2tf32(float x) {
    unsigned r;
    asm("cvt.rna.tf32.f32 %0, %1;" : "=r"(r) : "f"(x));
    return r;
}
__device__ __forceinline__ uint4 cvt4(float4 v) {
    uint4 r;
    r.x = f2tf32(v.x); r.y = f2tf32(v.y);
    r.z = f2tf32(v.z); r.w = f2tf32(v.w);
    return r;
}
__device__ __forceinline__ float fast_tanh(float x) {
    float y;
    asm("tanh.approx.f32 %0, %1;" : "=f"(y) : "f"(x));
    return y;
}
// mma.sync m16n8k8 tf32: D = A@B + C, fp32 accumulate
__device__ __forceinline__ void mma_tf32(float* c, const unsigned* a, const unsigned* b) {
    asm volatile(
        "mma.sync.aligned.m16n8k8.row.col.f32.tf32.tf32.f32 "
        "{%0,%1,%2,%3}, {%4,%5,%6,%7}, {%8,%9}, {%0,%1,%2,%3};"
        : "+f"(c[0]), "+f"(c[1]), "+f"(c[2]), "+f"(c[3])
        : "r"(a[0]), "r"(a[1]), "r"(a[2]), "r"(a[3]),
          "r"(b[0]), "r"(b[1]));
}

// ---------------------------------------------------------------------------
__global__ void init_y_kernel(const float* __restrict__ x) {
    int i = blockIdx.x * blockDim.x + threadIdx.x;
    if (i < B_ * D_) g_y[i] = x[i];
}

// ---------------------------------------------------------------------------
// GEMM1:  g_h[1024,2048] = tanh( Ain[1024,512] @ W1[512,2048] + b1 + t )
//   CTA tile 64x128, BK=16, 256 threads = 8 warps (2 M x 4 N), warp tile 32x32.
//   SMEM: As[m][k] stride 20 (pad 4), Bs[k][n] stride 136 (pad 8).
//   Fragment LDS conflict-free: bank(A)=20g+t4 (gaps>=4), bank(B)=8*t4+g.
__global__ __launch_bounds__(256) void gemm1_tanh(
    const float* __restrict__ W1, const float* __restrict__ b1,
    float t, int in_sel)
{
    __shared__ unsigned As[64 * 20];
    __shared__ unsigned Bs[16 * 136];

    const float* __restrict__ Ain = in_sel ? g_ytmp : g_y;

    const int tid  = threadIdx.x;
    const int lane = tid & 31;
    const int warp = tid >> 5;
    const int g    = lane >> 2;     // groupID
    const int t4   = lane & 3;      // threadID_in_group
    const int wm   = warp & 1;      // 0..1 (M)
    const int wn   = warp >> 1;     // 0..3 (N)

    const int bn0 = blockIdx.x * 128;
    const int bm0 = blockIdx.y * 64;

    // fill assignments
    const int am = tid >> 2;             // 0..63
    const int ak = (tid & 3) * 4;        // 0,4,8,12
    const int bk = tid >> 5;             // 0..7 (rows bk and bk+8)
    const int bn = (tid & 31) * 4;       // 0..124

    const float* Ap = Ain + (bm0 + am) * D_ + ak;
    const float* Bp = W1 + bk * H_ + bn0 + bn;

    float c[2][4][4];
#pragma unroll
    for (int i = 0; i < 2; i++)
#pragma unroll
        for (int j = 0; j < 4; j++)
#pragma unroll
            for (int e = 0; e < 4; e++) c[i][j][e] = 0.f;

    // prologue: prefetch slab 0
    float4 ra  = *reinterpret_cast<const float4*>(Ap);
    float4 rb0 = *reinterpret_cast<const float4*>(Bp);
    float4 rb1 = *reinterpret_cast<const float4*>(Bp + 8 * H_);

    *reinterpret_cast<uint4*>(&As[am * 20 + ak])        = cvt4(ra);
    *reinterpret_cast<uint4*>(&Bs[bk * 136 + bn])       = cvt4(rb0);
    *reinterpret_cast<uint4*>(&Bs[(bk + 8) * 136 + bn]) = cvt4(rb1);
    __syncthreads();

    for (int k0 = 16; k0 <= D_; k0 += 16) {
        const bool last = (k0 == D_);
        if (!last) {
            ra  = *reinterpret_cast<const float4*>(Ap + k0);
            rb0 = *reinterpret_cast<const float4*>(Bp + (size_t)k0 * H_);
            rb1 = *reinterpret_cast<const float4*>(Bp + (size_t)(k0 + 8) * H_);
        }
#pragma unroll
        for (int kk = 0; kk < 16; kk += 8) {
            unsigned a[2][4], b[4][2];
#pragma unroll
            for (int mt = 0; mt < 2; mt++) {
                int m0 = wm * 32 + mt * 16 + g;
                a[mt][0] = As[(m0)     * 20 + kk + t4];
                a[mt][1] = As[(m0 + 8) * 20 + kk + t4];
                a[mt][2] = As[(m0)     * 20 + kk + t4 + 4];
                a[mt][3] = As[(m0 + 8) * 20 + kk + t4 + 4];
            }
#pragma unroll
            for (int nt = 0; nt < 4; nt++) {
                int n0 = wn * 32 + nt * 8 + g;
                b[nt][0] = Bs[(kk + t4)     * 136 + n0];
                b[nt][1] = Bs[(kk + t4 + 4) * 136 + n0];
            }
#pragma unroll
            for (int mt = 0; mt < 2; mt++)
#pragma unroll
                for (int nt = 0; nt < 4; nt++)
                    mma_tf32(c[mt][nt], a[mt], b[nt]);
        }
        __syncthreads();
        if (!last) {
            *reinterpret_cast<uint4*>(&As[am * 20 + ak])        = cvt4(ra);
            *reinterpret_cast<uint4*>(&Bs[bk * 136 + bn])       = cvt4(rb0);
            *reinterpret_cast<uint4*>(&Bs[(bk + 8) * 136 + bn]) = cvt4(rb1);
            __syncthreads();
        }
    }

    // epilogue: tanh(c + b1[n] + t) -> g_h
#pragma unroll
    for (int mt = 0; mt < 2; mt++) {
        int row0 = bm0 + wm * 32 + mt * 16 + g;
#pragma unroll
        for (int nt = 0; nt < 4; nt++) {
            int col = bn0 + wn * 32 + nt * 8 + 2 * t4;
            float bb0 = b1[col] + t, bb1 = b1[col + 1] + t;
            float2 v0, v1;
            v0.x = fast_tanh(c[mt][nt][0] + bb0);
            v0.y = fast_tanh(c[mt][nt][1] + bb1);
            v1.x = fast_tanh(c[mt][nt][2] + bb0);
            v1.y = fast_tanh(c[mt][nt][3] + bb1);
            *reinterpret_cast<float2*>(&g_h[(size_t)row0 * H_ + col])       = v0;
            *reinterpret_cast<float2*>(&g_h[(size_t)(row0 + 8) * H_ + col]) = v1;
        }
    }
}

// ---------------------------------------------------------------------------
// GEMM2:  k[1024,512] = g_h[1024,2048] @ W2[2048,512] + b2, fused RK4 epilogue
//   CTA tile 64x64, BK=16, 128 threads = 4 warps (2 M x 2 N), warp tile 32x32.
//   SMEM: As stride 20, Bs stride 72.
// mode: 0 k1 / 1 k2 / 2 k3 / 3 k4 / 4 k4-final(write d_out)
__global__ __launch_bounds__(128) void gemm2_rk4(
    const float* __restrict__ W2, const float* __restrict__ b2,
    float dt, int mode, float* __restrict__ yout)
{
    __shared__ unsigned As[64 * 20];
    __shared__ unsigned Bs[16 * 72];

    const int tid  = threadIdx.x;
    const int lane = tid & 31;
    const int warp = tid >> 5;
    const int g    = lane >> 2;
    const int t4   = lane & 3;
    const int wm   = warp & 1;      // 0..1
    const int wn   = warp >> 1;     // 0..1

    const int bn0 = blockIdx.x * 64;
    const int bm0 = blockIdx.y * 64;

    // fill assignments (128 threads)
    const int am = tid >> 2;             // 0..31 (rows am and am+32)
    const int ak = (tid & 3) * 4;
    const int bk = tid >> 4;             // 0..7 (rows bk, bk+8)
    const int bn = (tid & 15) * 4;       // 0..60

    const float* Ap = g_h + (size_t)(bm0 + am) * H_ + ak;
    const float* Bp = W2 + (size_t)bk * D_ + bn0 + bn;

    float c[2][4][4];
#pragma unroll
    for (int i = 0; i < 2; i++)
#pragma unroll
        for (int j = 0; j < 4; j++)
#pragma unroll
            for (int e = 0; e < 4; e++) c[i][j][e] = 0.f;

    float4 ra0 = *reinterpret_cast<const float4*>(Ap);
    float4 ra1 = *reinterpret_cast<const float4*>(Ap + (size_t)32 * H_);
    float4 rb0 = *reinterpret_cast<const float4*>(Bp);
    float4 rb1 = *reinterpret_cast<const float4*>(Bp + 8 * D_);

    *reinterpret_cast<uint4*>(&As[am * 20 + ak])         = cvt4(ra0);
    *reinterpret_cast<uint4*>(&As[(am + 32) * 20 + ak])  = cvt4(ra1);
    *reinterpret_cast<uint4*>(&Bs[bk * 72 + bn])         = cvt4(rb0);
    *reinterpret_cast<uint4*>(&Bs[(bk + 8) * 72 + bn])   = cvt4(rb1);
    __syncthreads();

    for (int k0 = 16; k0 <= H_; k0 += 16) {
        const bool last = (k0 == H_);
        if (!last) {
            ra0 = *reinterpret_cast<const float4*>(Ap + k0);
            ra1 = *reinterpret_cast<const float4*>(Ap + (size_t)32 * H_ + k0);
            rb0 = *reinterpret_cast<const float4*>(Bp + (size_t)k0 * D_);
            rb1 = *reinterpret_cast<const float4*>(Bp + (size_t)(k0 + 8) * D_);
        }
#pragma unroll
        for (int kk = 0; kk < 16; kk += 8) {
            unsigned a[2][4], b[4][2];
#pragma unroll
            for (int mt = 0; mt < 2; mt++) {
                int m0 = wm * 32 + mt * 16 + g;
                a[mt][0] = As[(m0)     * 20 + kk + t4];
                a[mt][1] = As[(m0 + 8) * 20 + kk + t4];
                a[mt][2] = As[(m0)     * 20 + kk + t4 + 4];
                a[mt][3] = As[(m0 + 8) * 20 + kk + t4 + 4];
            }
#pragma unroll
            for (int nt = 0; nt < 4; nt++) {
                int n0 = wn * 32 + nt * 8 + g;
                b[nt][0] = Bs[(kk + t4)     * 72 + n0];
                b[nt][1] = Bs[(kk + t4 + 4) * 72 + n0];
            }
#pragma unroll
            for (int mt = 0; mt < 2; mt++)
#pragma unroll
                for (int nt = 0; nt < 4; nt++)
                    mma_tf32(c[mt][nt], a[mt], b[nt]);
        }
        __syncthreads();
        if (!last) {
            *reinterpret_cast<uint4*>(&As[am * 20 + ak])        = cvt4(ra0);
            *reinterpret_cast<uint4*>(&As[(am + 32) * 20 + ak]) = cvt4(ra1);
            *reinterpret_cast<uint4*>(&Bs[bk * 72 + bn])        = cvt4(rb0);
            *reinterpret_cast<uint4*>(&Bs[(bk + 8) * 72 + bn])  = cvt4(rb1);
            __syncthreads();
        }
    }

    const float half_dt  = 0.5f * dt;
    const float sixth_dt = dt * (1.0f / 6.0f);

#pragma unroll
    for (int mt = 0; mt < 2; mt++) {
        int row0 = bm0 + wm * 32 + mt * 16 + g;
#pragma unroll
        for (int nt = 0; nt < 4; nt++) {
            int col = bn0 + wn * 32 + nt * 8 + 2 * t4;
            float bb0 = b2[col], bb1 = b2[col + 1];
#pragma unroll
            for (int rr = 0; rr < 2; rr++) {
                int row = row0 + rr * 8;
                size_t idx = (size_t)row * D_ + col;
                float kv0 = c[mt][nt][rr * 2 + 0] + bb0;
                float kv1 = c[mt][nt][rr * 2 + 1] + bb1;
                if (mode == 0) {
                    float2 y = *reinterpret_cast<const float2*>(&g_y[idx]);
                    float2 ac, yt;
                    ac.x = kv0;                ac.y = kv1;
                    yt.x = y.x + half_dt*kv0;  yt.y = y.y + half_dt*kv1;
                    *reinterpret_cast<float2*>(&g_acc[idx])  = ac;
                    *reinterpret_cast<float2*>(&g_ytmp[idx]) = yt;
                } else if (mode == 1) {
                    float2 y  = *reinterpret_cast<const float2*>(&g_y[idx]);
                    float2 ac = *reinterpret_cast<const float2*>(&g_acc[idx]);
                    ac.x += 2.f*kv0;           ac.y += 2.f*kv1;
                    float2 yt;
                    yt.x = y.x + half_dt*kv0;  yt.y = y.y + half_dt*kv1;
                    *reinterpret_cast<float2*>(&g_acc[idx])  = ac;
                    *reinterpret_cast<float2*>(&g_ytmp[idx]) = yt;
                } else if (mode == 2) {
                    float2 y  = *reinterpret_cast<const float2*>(&g_y[idx]);
                    float2 ac = *reinterpret_cast<const float2*>(&g_acc[idx]);
                    ac.x += 2.f*kv0;           ac.y += 2.f*kv1;
                    float2 yt;
                    yt.x = y.x + dt*kv0;       yt.y = y.y + dt*kv1;
                    *reinterpret_cast<float2*>(&g_acc[idx])  = ac;
                    *reinterpret_cast<float2*>(&g_ytmp[idx]) = yt;
                } else if (mode == 3) {
                    float2 y  = *reinterpret_cast<const float2*>(&g_y[idx]);
                    float2 ac = *reinterpret_cast<const float2*>(&g_acc[idx]);
                    y.x += sixth_dt * (ac.x + kv0);
                    y.y += sixth_dt * (ac.y + kv1);
                    *reinterpret_cast<float2*>(&g_y[idx]) = y;
                } else {
                    float2 y  = *reinterpret_cast<const float2*>(&g_y[idx]);
                    float2 ac = *reinterpret_cast<const float2*>(&g_acc[idx]);
                    float2 o;
                    o.x = y.x + sixth_dt * (ac.x + kv0);
                    o.y = y.y + sixth_dt * (ac.y + kv1);
                    *reinterpret_cast<float2*>(&yout[idx]) = o;
                }
            }
        }
    }
}

// ---------------------------------------------------------------------------
extern "C" void kernel_launch(void* const* d_in, const int* in_sizes, int n_in,
                              void* d_out, int out_size)
{
    const float* x  = (const float*)d_in[0];   // [1024, 512]
    const float* W1 = (const float*)d_in[1];   // [512, 2048]
    const float* b1 = (const float*)d_in[2];   // [2048]
    const float* W2 = (const float*)d_in[3];   // [2048, 512]
    const float* b2 = (const float*)d_in[4];   // [512]
    float* out = (float*)d_out;                // [1024, 512]

    const float dt = 1.0f / (float)NSTEPS;

    init_y_kernel<<<(B_ * D_ + 255) / 256, 256>>>(x);

    dim3 grid1(H_ / 128, B_ / 64);   // (16,16) = 256 CTAs
    dim3 grid2(D_ / 64,  B_ / 64);   // (8,16)  = 128 CTAs

    for (int s = 0; s < NSTEPS; s++) {
        float t = dt * (float)s;

        gemm1_tanh<<<grid1, 256>>>(W1, b1, t, /*in_sel=*/0);
        gemm2_rk4 <<<grid2, 128>>>(W2, b2, dt, /*mode=*/0, out);

        gemm1_tanh<<<grid1, 256>>>(W1, b1, t + 0.5f * dt, /*in_sel=*/1);
        gemm2_rk4 <<<grid2, 128>>>(W2, b2, dt, /*mode=*/1, out);

        gemm1_tanh<<<grid1, 256>>>(W1, b1, t + 0.5f * dt, /*in_sel=*/1);
        gemm2_rk4 <<<grid2, 128>>>(W2, b2, dt, /*mode=*/2, out);

        gemm1_tanh<<<grid1, 256>>>(W1, b1, t + dt, /*in_sel=*/1);
        int mode = (s == NSTEPS - 1) ? 4 : 3;
        gemm2_rk4 <<<grid2, 128>>>(W2, b2, dt, mode, out);
    }
}

// round 3
// speedup vs baseline: 3.9812x; 1.8798x over previous
#include <cuda_runtime.h>
#include <math.h>

// Problem dims (fixed by the reference)
#define B_  1024
#define D_  512
#define H_  2048
#define NSTEPS 16

// -------- device scratch (allocation-free: static __device__ globals) --------
__device__ float g_y   [B_ * D_];   // current state y
__device__ float g_ytmp[B_ * D_];   // y + c*k  (input to next f eval)
__device__ float g_acc [B_ * D_];   // RK4 accumulator k1 + 2k2 + 2k3
__device__ float g_h   [B_ * H_];   // hidden activations tanh(...)

// ---------------------------------------------------------------------------
__device__ __forceinline__ float fast_tanh(float x) {
    float y;
    asm("tanh.approx.f32 %0, %1;" : "=f"(y) : "f"(x));
    return y;
}
// mma.sync m16n8k8 tf32: D = A@B + C, fp32 accumulate.
// Operands are raw fp32 bit patterns; HW uses the tf32 subset (RZ truncation).
__device__ __forceinline__ void mma_tf32(float* c, const unsigned* a, const unsigned* b) {
    asm volatile(
        "mma.sync.aligned.m16n8k8.row.col.f32.tf32.tf32.f32 "
        "{%0,%1,%2,%3}, {%4,%5,%6,%7}, {%8,%9}, {%0,%1,%2,%3};"
        : "+f"(c[0]), "+f"(c[1]), "+f"(c[2]), "+f"(c[3])
        : "r"(a[0]), "r"(a[1]), "r"(a[2]), "r"(a[3]),
          "r"(b[0]), "r"(b[1]));
}
__device__ __forceinline__ void cp_async16(void* smem_dst, const void* gmem_src) {
    unsigned s = (unsigned)__cvta_generic_to_shared(smem_dst);
    asm volatile("cp.async.ca.shared.global [%0], [%1], 16;\n" :: "r"(s), "l"(gmem_src));
}
__device__ __forceinline__ void cp_commit() {
    asm volatile("cp.async.commit_group;\n");
}
__device__ __forceinline__ void cp_wait1() {
    asm volatile("cp.async.wait_group 1;\n");
}
__device__ __forceinline__ void cp_wait0() {
    asm volatile("cp.async.wait_group 0;\n");
}

// ---------------------------------------------------------------------------
__global__ void init_y_kernel(const float* __restrict__ x) {
    int i = blockIdx.x * blockDim.x + threadIdx.x;
    if (i < B_ * D_) g_y[i] = x[i];
}

// ---------------------------------------------------------------------------
// GEMM1:  g_h[1024,2048] = tanh( Ain[1024,512] @ W1[512,2048] + b1 + t )
//   CTA tile 128x128, BK=16, 256 threads = 8 warps (2 M x 4 N), warp tile 64x32.
//   2-stage cp.async pipeline. SMEM: As stride 20 (80B, 16B-aligned),
//   Bs stride 136 (544B, 16B-aligned). Frag LDS conflict-free:
//   bank(A) = 20g + t4 (distinct), bank(B) = 8*t4 + g (distinct).
__global__ __launch_bounds__(256) void gemm1_tanh(
    const float* __restrict__ W1, const float* __restrict__ b1,
    float t, int in_sel)
{
    __shared__ float As[2][128 * 20];
    __shared__ float Bs[2][16 * 136];

    const float* __restrict__ Ain = in_sel ? g_ytmp : g_y;

    const int tid  = threadIdx.x;
    const int lane = tid & 31;
    const int warp = tid >> 5;
    const int g    = lane >> 2;     // groupID 0..7
    const int t4   = lane & 3;      // thread-in-group 0..3
    const int wm   = warp & 1;      // 0..1 -> m offset wm*64
    const int wn   = warp >> 1;     // 0..3 -> n offset wn*32

    const int bn0 = blockIdx.x * 128;
    const int bm0 = blockIdx.y * 128;

    // fill mapping (2 chunks of 16B each for A and B per thread per slab)
    // A: 128 rows x 16 cols -> 512 chunks; id: r=id>>2, c=(id&3)*4
    // B: 16 rows x 128 cols -> 512 chunks; id: r=id>>5, c=(id&31)*4
    auto load_slab = [&](int k0, int s) {
#pragma unroll
        for (int i = 0; i < 2; i++) {
            int id = tid + 256 * i;
            int r = id >> 2, c = (id & 3) * 4;
            cp_async16(&As[s][r * 20 + c], &Ain[(size_t)(bm0 + r) * D_ + k0 + c]);
        }
#pragma unroll
        for (int i = 0; i < 2; i++) {
            int id = tid + 256 * i;
            int r = id >> 5, c = (id & 31) * 4;
            cp_async16(&Bs[s][r * 136 + c], &W1[(size_t)(k0 + r) * H_ + bn0 + c]);
        }
        cp_commit();
    };

    float c[4][4][4];
#pragma unroll
    for (int i = 0; i < 4; i++)
#pragma unroll
        for (int j = 0; j < 4; j++)
#pragma unroll
            for (int e = 0; e < 4; e++) c[i][j][e] = 0.f;

    const int NS = D_ / 16;   // 32 slabs
    load_slab(0, 0);

    for (int si = 0; si < NS; si++) {
        const int s = si & 1;
        const bool more = (si + 1 < NS);
        if (more) { load_slab((si + 1) * 16, s ^ 1); cp_wait1(); }
        else      { cp_wait0(); }
        __syncthreads();

        const unsigned* Asu = reinterpret_cast<const unsigned*>(As[s]);
        const unsigned* Bsu = reinterpret_cast<const unsigned*>(Bs[s]);
#pragma unroll
        for (int kk = 0; kk < 16; kk += 8) {
            unsigned a[4][4], b[4][2];
#pragma unroll
            for (int mt = 0; mt < 4; mt++) {
                int m0 = wm * 64 + mt * 16 + g;
                a[mt][0] = Asu[(m0)     * 20 + kk + t4];
                a[mt][1] = Asu[(m0 + 8) * 20 + kk + t4];
                a[mt][2] = Asu[(m0)     * 20 + kk + t4 + 4];
                a[mt][3] = Asu[(m0 + 8) * 20 + kk + t4 + 4];
            }
#pragma unroll
            for (int nt = 0; nt < 4; nt++) {
                int n0 = wn * 32 + nt * 8 + g;
                b[nt][0] = Bsu[(kk + t4)     * 136 + n0];
                b[nt][1] = Bsu[(kk + t4 + 4) * 136 + n0];
            }
#pragma unroll
            for (int mt = 0; mt < 4; mt++)
#pragma unroll
                for (int nt = 0; nt < 4; nt++)
                    mma_tf32(c[mt][nt], a[mt], b[nt]);
        }
        __syncthreads();
    }

    // epilogue: tanh(c + b1[n] + t) -> g_h
#pragma unroll
    for (int mt = 0; mt < 4; mt++) {
        int row0 = bm0 + wm * 64 + mt * 16 + g;
#pragma unroll
        for (int nt = 0; nt < 4; nt++) {
            int col = bn0 + wn * 32 + nt * 8 + 2 * t4;
            float bb0 = b1[col] + t, bb1 = b1[col + 1] + t;
            float2 v0, v1;
            v0.x = fast_tanh(c[mt][nt][0] + bb0);
            v0.y = fast_tanh(c[mt][nt][1] + bb1);
            v1.x = fast_tanh(c[mt][nt][2] + bb0);
            v1.y = fast_tanh(c[mt][nt][3] + bb1);
            *reinterpret_cast<float2*>(&g_h[(size_t)row0 * H_ + col])       = v0;
            *reinterpret_cast<float2*>(&g_h[(size_t)(row0 + 8) * H_ + col]) = v1;
        }
    }
}

// ---------------------------------------------------------------------------
// GEMM2:  k[1024,512] = g_h[1024,2048] @ W2[2048,512] + b2, fused RK4 epilogue
//   CTA tile 64x64, BK=32, 256 threads = 8 warps (2 M x 4 N), warp tile 32x16.
//   2-stage cp.async pipeline. SMEM: As stride 36 (144B ok), Bs stride 72 (288B ok).
//   bank(A) = (36g + t4) mod 32 = 4g + t4 (distinct), bank(B) = 8*t4 + g (distinct).
// mode: 0 k1 / 1 k2 / 2 k3 / 3 k4 / 4 k4-final(write d_out)
__global__ __launch_bounds__(256) void gemm2_rk4(
    const float* __restrict__ W2, const float* __restrict__ b2,
    float dt, int mode, float* __restrict__ yout)
{
    __shared__ float As[2][64 * 36];
    __shared__ float Bs[2][32 * 72];

    const int tid  = threadIdx.x;
    const int lane = tid & 31;
    const int warp = tid >> 5;
    const int g    = lane >> 2;
    const int t4   = lane & 3;
    const int wm   = warp & 1;      // 0..1 -> m offset wm*32
    const int wn   = warp >> 1;     // 0..3 -> n offset wn*16

    const int bn0 = blockIdx.x * 64;
    const int bm0 = blockIdx.y * 64;

    // A: 64 rows x 32 cols -> 512 chunks; id: r=id>>3, c=(id&7)*4
    // B: 32 rows x 64 cols -> 512 chunks; id: r=id>>4, c=(id&15)*4
    auto load_slab = [&](int k0, int s) {
#pragma unroll
        for (int i = 0; i < 2; i++) {
            int id = tid + 256 * i;
            int r = id >> 3, c = (id & 7) * 4;
            cp_async16(&As[s][r * 36 + c], &g_h[(size_t)(bm0 + r) * H_ + k0 + c]);
        }
#pragma unroll
        for (int i = 0; i < 2; i++) {
            int id = tid + 256 * i;
            int r = id >> 4, c = (id & 15) * 4;
            cp_async16(&Bs[s][r * 72 + c], &W2[(size_t)(k0 + r) * D_ + bn0 + c]);
        }
        cp_commit();
    };

    float c[2][2][4];
#pragma unroll
    for (int i = 0; i < 2; i++)
#pragma unroll
        for (int j = 0; j < 2; j++)
#pragma unroll
            for (int e = 0; e < 4; e++) c[i][j][e] = 0.f;

    const int NS = H_ / 32;   // 64 slabs
    load_slab(0, 0);

    for (int si = 0; si < NS; si++) {
        const int s = si & 1;
        const bool more = (si + 1 < NS);
        if (more) { load_slab((si + 1) * 32, s ^ 1); cp_wait1(); }
        else      { cp_wait0(); }
        __syncthreads();

        const unsigned* Asu = reinterpret_cast<const unsigned*>(As[s]);
        const unsigned* Bsu = reinterpret_cast<const unsigned*>(Bs[s]);
#pragma unroll
        for (int kk = 0; kk < 32; kk += 8) {
            unsigned a[2][4], b[2][2];
#pragma unroll
            for (int mt = 0; mt < 2; mt++) {
                int m0 = wm * 32 + mt * 16 + g;
                a[mt][0] = Asu[(m0)     * 36 + kk + t4];
                a[mt][1] = Asu[(m0 + 8) * 36 + kk + t4];
                a[mt][2] = Asu[(m0)     * 36 + kk + t4 + 4];
                a[mt][3] = Asu[(m0 + 8) * 36 + kk + t4 + 4];
            }
#pragma unroll
            for (int nt = 0; nt < 2; nt++) {
                int n0 = wn * 16 + nt * 8 + g;
                b[nt][0] = Bsu[(kk + t4)     * 72 + n0];
                b[nt][1] = Bsu[(kk + t4 + 4) * 72 + n0];
            }
#pragma unroll
            for (int mt = 0; mt < 2; mt++)
#pragma unroll
                for (int nt = 0; nt < 2; nt++)
                    mma_tf32(c[mt][nt], a[mt], b[nt]);
        }
        __syncthreads();
    }

    const float half_dt  = 0.5f * dt;
    const float sixth_dt = dt * (1.0f / 6.0f);

#pragma unroll
    for (int mt = 0; mt < 2; mt++) {
        int row0 = bm0 + wm * 32 + mt * 16 + g;
#pragma unroll
        for (int nt = 0; nt < 2; nt++) {
            int col = bn0 + wn * 16 + nt * 8 + 2 * t4;
            float bb0 = b2[col], bb1 = b2[col + 1];
#pragma unroll
            for (int rr = 0; rr < 2; rr++) {
                int row = row0 + rr * 8;
                size_t idx = (size_t)row * D_ + col;
                float kv0 = c[mt][nt][rr * 2 + 0] + bb0;
                float kv1 = c[mt][nt][rr * 2 + 1] + bb1;
                if (mode == 0) {
                    float2 y = *reinterpret_cast<const float2*>(&g_y[idx]);
                    float2 ac, yt;
                    ac.x = kv0;                 ac.y = kv1;
                    yt.x = y.x + half_dt * kv0; yt.y = y.y + half_dt * kv1;
                    *reinterpret_cast<float2*>(&g_acc[idx])  = ac;
                    *reinterpret_cast<float2*>(&g_ytmp[idx]) = yt;
                } else if (mode == 1) {
                    float2 y  = *reinterpret_cast<const float2*>(&g_y[idx]);
                    float2 ac = *reinterpret_cast<const float2*>(&g_acc[idx]);
                    ac.x += 2.f * kv0;          ac.y += 2.f * kv1;
                    float2 yt;
                    yt.x = y.x + half_dt * kv0; yt.y = y.y + half_dt * kv1;
                    *reinterpret_cast<float2*>(&g_acc[idx])  = ac;
                    *reinterpret_cast<float2*>(&g_ytmp[idx]) = yt;
                } else if (mode == 2) {
                    float2 y  = *reinterpret_cast<const float2*>(&g_y[idx]);
                    float2 ac = *reinterpret_cast<const float2*>(&g_acc[idx]);
                    ac.x += 2.f * kv0;          ac.y += 2.f * kv1;
                    float2 yt;
                    yt.x = y.x + dt * kv0;      yt.y = y.y + dt * kv1;
                    *reinterpret_cast<float2*>(&g_acc[idx])  = ac;
                    *reinterpret_cast<float2*>(&g_ytmp[idx]) = yt;
                } else if (mode == 3) {
                    float2 y  = *reinterpret_cast<const float2*>(&g_y[idx]);
                    float2 ac = *reinterpret_cast<const float2*>(&g_acc[idx]);
                    y.x += sixth_dt * (ac.x + kv0);
                    y.y += sixth_dt * (ac.y + kv1);
                    *reinterpret_cast<float2*>(&g_y[idx]) = y;
                } else {
                    float2 y  = *reinterpret_cast<const float2*>(&g_y[idx]);
                    float2 ac = *reinterpret_cast<const float2*>(&g_acc[idx]);
                    float2 o;
                    o.x = y.x + sixth_dt * (ac.x + kv0);
                    o.y = y.y + sixth_dt * (ac.y + kv1);
                    *reinterpret_cast<float2*>(&yout[idx]) = o;
                }
            }
        }
    }
}

// ---------------------------------------------------------------------------
extern "C" void kernel_launch(void* const* d_in, const int* in_sizes, int n_in,
                              void* d_out, int out_size)
{
    const float* x  = (const float*)d_in[0];   // [1024, 512]
    const float* W1 = (const float*)d_in[1];   // [512, 2048]
    const float* b1 = (const float*)d_in[2];   // [2048]
    const float* W2 = (const float*)d_in[3];   // [2048, 512]
    const float* b2 = (const float*)d_in[4];   // [512]
    float* out = (float*)d_out;                // [1024, 512]

    const float dt = 1.0f / (float)NSTEPS;

    init_y_kernel<<<(B_ * D_ + 255) / 256, 256>>>(x);

    dim3 grid1(H_ / 128, B_ / 128);  // (16,8)  = 128 CTAs
    dim3 grid2(D_ / 64,  B_ / 64);   // (8,16)  = 128 CTAs

    for (int s = 0; s < NSTEPS; s++) {
        float t = dt * (float)s;

        gemm1_tanh<<<grid1, 256>>>(W1, b1, t, /*in_sel=*/0);
        gemm2_rk4 <<<grid2, 256>>>(W2, b2, dt, /*mode=*/0, out);

        gemm1_tanh<<<grid1, 256>>>(W1, b1, t + 0.5f * dt, /*in_sel=*/1);
        gemm2_rk4 <<<grid2, 256>>>(W2, b2, dt, /*mode=*/1, out);

        gemm1_tanh<<<grid1, 256>>>(W1, b1, t + 0.5f * dt, /*in_sel=*/1);
        gemm2_rk4 <<<grid2, 256>>>(W2, b2, dt, /*mode=*/2, out);

        gemm1_tanh<<<grid1, 256>>>(W1, b1, t + dt, /*in_sel=*/1);
        int mode = (s == NSTEPS - 1) ? 4 : 3;
        gemm2_rk4 <<<grid2, 256>>>(W2, b2, dt, mode, out);
    }
}